// round 1
// baseline (speedup 1.0000x reference)
#include <cuda_runtime.h>
#include <cuda_bf16.h>

// ----------------------------------------------------------------------------
// LocalGridAttention, fp32 baseline:
//   1) transpose_w : Wq/Wk/Wv [O][C] -> [C][O] (coalesced GEMM A-loads)
//   2) gemm_proj   : out[b][o][j] = (sum_c W[o][c]*F[b][c][j] + bias[o]) * scale
//                    128x128x8 SGEMM, 8x8 per thread, f32x2 packed FMA
//   3) attn_kernel : per (b,head,y,x): 16 local logits, softmax, gather V
// Shapes fixed per problem instance: B=2, C=256, heads=8, hd=32,
// h=w=64 (HW=4096), hf=wf=256 (HWF=65536), rH=rW=4.
// ----------------------------------------------------------------------------

#define C_DIM 256
#define HW    4096
#define HWF   65536

// Scratch (device globals: allocation-free per harness rules)
__device__ float g_wt[3 * C_DIM * C_DIM];           // transposed weights
__device__ float g_q[(size_t)2 * C_DIM * HW];       // 8.4 MB
__device__ float g_k[(size_t)2 * C_DIM * HWF];      // 128 MB
__device__ float g_v[(size_t)2 * C_DIM * HWF];      // 128 MB

// ---------------------------------------------------------------- transpose
__global__ void transpose_w(const float* __restrict__ Wq,
                            const float* __restrict__ Wk,
                            const float* __restrict__ Wv,
                            float* __restrict__ dst3) {
    const float* S = (blockIdx.z == 0) ? Wq : (blockIdx.z == 1) ? Wk : Wv;
    float* D = dst3 + (size_t)blockIdx.z * C_DIM * C_DIM;
    __shared__ float tile[32][33];
    int c = blockIdx.x * 32 + threadIdx.x;   // column (contiguous in src)
    int o = blockIdx.y * 32 + threadIdx.y;   // row
    tile[threadIdx.y][threadIdx.x] = S[o * C_DIM + c];
    __syncthreads();
    // D[c][o]
    int co = blockIdx.x * 32 + threadIdx.y;
    int oo = blockIdx.y * 32 + threadIdx.x;
    D[co * C_DIM + oo] = tile[threadIdx.x][threadIdx.y];
}

// ---------------------------------------------------------------- gemm
#define BM 128
#define BN 128
#define BK 8

__global__ __launch_bounds__(256)
void gemm_proj(const float* __restrict__ Wt,    // [C][O], Wt[c*256+o]=W[o][c]
               const float* __restrict__ bias,  // [O]
               const float* __restrict__ F,     // [B][C][J]
               float* __restrict__ Out,         // [B][O][J]
               int J, float scale) {
    const int jt = blockIdx.x;
    const int ot = blockIdx.y;   // 0..1
    const int b  = blockIdx.z;
    const int t  = threadIdx.x;  // 0..255
    const int tx = t & 15;       // j-group  (8 cols each)
    const int ty = t >> 4;       // o-group  (8 rows each)

    const float* Fb = F + (size_t)b * C_DIM * J + (size_t)jt * BN;
    float* Ob = Out + (size_t)b * C_DIM * J + (size_t)ot * BM * J + (size_t)jt * BN;
    const float* Wb = Wt + ot * BM;

    __shared__ float As[BK][BM];
    __shared__ float Bs[BK][BN];

    // f32x2 accumulators: acc[i][jj] = outputs (o=ty*8+i, j=tx*8+2*jj..+1)
    unsigned long long acc[8][4];
#pragma unroll
    for (int i = 0; i < 8; i++)
#pragma unroll
        for (int jj = 0; jj < 4; jj++) acc[i][jj] = 0ull;

    const int lk  = t >> 5;          // 0..7  (k row)
    const int lo4 = (t & 31) * 4;    // 0..124 (col, float4)

    for (int c0 = 0; c0 < C_DIM; c0 += BK) {
        *(float4*)&As[lk][lo4] = *(const float4*)&Wb[(size_t)(c0 + lk) * C_DIM + lo4];
        *(float4*)&Bs[lk][lo4] = *(const float4*)&Fb[(size_t)(c0 + lk) * J + lo4];
        __syncthreads();
#pragma unroll
        for (int k = 0; k < BK; k++) {
            unsigned long long b2[4];
            const unsigned long long* bp =
                (const unsigned long long*)&Bs[k][tx * 8];
            b2[0] = bp[0]; b2[1] = bp[1]; b2[2] = bp[2]; b2[3] = bp[3];

            float4 a0 = *(const float4*)&As[k][ty * 8];
            float4 a1 = *(const float4*)&As[k][ty * 8 + 4];
            float av[8] = {a0.x, a0.y, a0.z, a0.w, a1.x, a1.y, a1.z, a1.w};
#pragma unroll
            for (int i = 0; i < 8; i++) {
                unsigned long long a2;
                unsigned int au = __float_as_uint(av[i]);
                asm("mov.b64 %0, {%1, %1};" : "=l"(a2) : "r"(au));
#pragma unroll
                for (int jj = 0; jj < 4; jj++) {
                    asm("fma.rn.f32x2 %0, %1, %2, %0;"
                        : "+l"(acc[i][jj]) : "l"(a2), "l"(b2[jj]));
                }
            }
        }
        __syncthreads();
    }

    // epilogue: (acc + bias) * scale
#pragma unroll
    for (int i = 0; i < 8; i++) {
        float bi = bias[ot * BM + ty * 8 + i];
        float r[8];
#pragma unroll
        for (int jj = 0; jj < 4; jj++) {
            unsigned int lo, hi;
            asm("mov.b64 {%0, %1}, %2;" : "=r"(lo), "=r"(hi) : "l"(acc[i][jj]));
            r[2 * jj]     = (__uint_as_float(lo) + bi) * scale;
            r[2 * jj + 1] = (__uint_as_float(hi) + bi) * scale;
        }
        float* orow = Ob + (size_t)(ty * 8 + i) * J + tx * 8;
        *(float4*)&orow[0] = make_float4(r[0], r[1], r[2], r[3]);
        *(float4*)&orow[4] = make_float4(r[4], r[5], r[6], r[7]);
    }
}

// ---------------------------------------------------------------- attention
__global__ __launch_bounds__(256)
void attn_kernel(const float* __restrict__ q,   // [B][256][64][64], pre-scaled
                 const float* __restrict__ k,   // [B][256][256][256]
                 const float* __restrict__ v,
                 float* __restrict__ out) {     // [B][256][64][64]
    int t = blockIdx.x * blockDim.x + threadIdx.x;  // 0..65535
    int x    = t & 63;
    int y    = (t >> 6) & 63;
    int head = (t >> 12) & 7;
    int b    = t >> 15;

    const size_t chq = (size_t)(b * C_DIM + head * 32);
    const float* qb = q + chq * HW + y * 64 + x;
    const size_t fbase = chq * HWF + (size_t)(4 * y) * 256 + 4 * x;
    const float* kb = k + fbase;
    const float* vb = v + fbase;

    float logit[16];
#pragma unroll
    for (int p = 0; p < 16; p++) logit[p] = 0.f;

#pragma unroll 4
    for (int d = 0; d < 32; d++) {
        float qd = qb[(size_t)d * HW];
#pragma unroll
        for (int dy = 0; dy < 4; dy++) {
            float4 kv = *(const float4*)(kb + (size_t)d * HWF + dy * 256);
            logit[dy * 4 + 0] = fmaf(qd, kv.x, logit[dy * 4 + 0]);
            logit[dy * 4 + 1] = fmaf(qd, kv.y, logit[dy * 4 + 1]);
            logit[dy * 4 + 2] = fmaf(qd, kv.z, logit[dy * 4 + 2]);
            logit[dy * 4 + 3] = fmaf(qd, kv.w, logit[dy * 4 + 3]);
        }
    }

    // softmax over the 16 local positions
    float m = logit[0];
#pragma unroll
    for (int p = 1; p < 16; p++) m = fmaxf(m, logit[p]);
    float s = 0.f;
#pragma unroll
    for (int p = 0; p < 16; p++) {
        logit[p] = __expf(logit[p] - m);
        s += logit[p];
    }
    float inv = 1.f / s;
#pragma unroll
    for (int p = 0; p < 16; p++) logit[p] *= inv;

    // gather V
    float* ob = out + chq * HW + y * 64 + x;
#pragma unroll 4
    for (int d = 0; d < 32; d++) {
        float sum = 0.f;
#pragma unroll
        for (int dy = 0; dy < 4; dy++) {
            float4 vv = *(const float4*)(vb + (size_t)d * HWF + dy * 256);
            sum = fmaf(logit[dy * 4 + 0], vv.x, sum);
            sum = fmaf(logit[dy * 4 + 1], vv.y, sum);
            sum = fmaf(logit[dy * 4 + 2], vv.z, sum);
            sum = fmaf(logit[dy * 4 + 3], vv.w, sum);
        }
        ob[(size_t)d * HW] = sum;
    }
}

// ---------------------------------------------------------------- launch
extern "C" void kernel_launch(void* const* d_in, const int* in_sizes, int n_in,
                              void* d_out, int out_size) {
    const float* x  = (const float*)d_in[0];
    const float* fm = (const float*)d_in[1];
    const float* Wq = (const float*)d_in[2];
    const float* bq = (const float*)d_in[3];
    const float* Wk = (const float*)d_in[4];
    const float* bk = (const float*)d_in[5];
    const float* Wv = (const float*)d_in[6];
    const float* bv = (const float*)d_in[7];
    float* out = (float*)d_out;

    float *wt, *q, *k, *v;
    cudaGetSymbolAddress((void**)&wt, g_wt);
    cudaGetSymbolAddress((void**)&q,  g_q);
    cudaGetSymbolAddress((void**)&k,  g_k);
    cudaGetSymbolAddress((void**)&v,  g_v);

    const float scaling = 0.17677669529663687f;  // (C/heads)^-0.5 = 32^-0.5

    transpose_w<<<dim3(8, 8, 3), dim3(32, 32)>>>(Wq, Wk, Wv, wt);
    // Q: J=4096, fused scaling
    gemm_proj<<<dim3(HW / BN, 2, 2), 256>>>(wt, bq, x, q, HW, scaling);
    // K, V: J=65536
    gemm_proj<<<dim3(HWF / BN, 2, 2), 256>>>(wt + C_DIM * C_DIM, bk, fm, k, HWF, 1.0f);
    gemm_proj<<<dim3(HWF / BN, 2, 2), 256>>>(wt + 2 * C_DIM * C_DIM, bv, fm, v, HWF, 1.0f);
    attn_kernel<<<(2 * 8 * HW) / 256, 256>>>(q, k, v, out);
}

// round 7
// speedup vs baseline: 1.8181x; 1.8181x over previous
#include <cuda_runtime.h>
#include <cuda_bf16.h>
#include <stdint.h>

#define C_DIM 256
#define HW    4096
#define HWF   65536

// ------------------------------ scratch (same set as the R1 kernel that passed)
__device__ float g_q[(size_t)2 * C_DIM * HW];       // 8.4 MB
__device__ float g_k[(size_t)2 * C_DIM * HWF];      // 134 MB
__device__ float g_v[(size_t)2 * C_DIM * HWF];      // 134 MB

// ------------------------------ helpers
__device__ __forceinline__ uint32_t smem_u32(const void* p) {
    return (uint32_t)__cvta_generic_to_shared(p);
}
__device__ __forceinline__ void cp16(uint32_t s, const void* g) {
    asm volatile("cp.async.cg.shared.global [%0], [%1], 16;\n" :: "r"(s), "l"(g) : "memory");
}
#define CP_COMMIT() asm volatile("cp.async.commit_group;\n" ::: "memory")
#define CP_WAIT1()  asm volatile("cp.async.wait_group 1;\n" ::: "memory")
#define CP_WAIT0()  asm volatile("cp.async.wait_group 0;\n" ::: "memory")

__device__ __forceinline__ void mma16816(float* d, const uint32_t* a, const uint32_t* b) {
    asm volatile(
        "mma.sync.aligned.m16n8k16.row.col.f32.bf16.bf16.f32 "
        "{%0,%1,%2,%3}, {%4,%5,%6,%7}, {%8,%9}, {%0,%1,%2,%3};"
        : "+f"(d[0]), "+f"(d[1]), "+f"(d[2]), "+f"(d[3])
        : "r"(a[0]), "r"(a[1]), "r"(a[2]), "r"(a[3]), "r"(b[0]), "r"(b[1]));
}

// split a float pair into bf16x2 hi (rounded) and bf16x2 lo (residual).
// low 16 bits hold f0, high 16 bits hold f1 (k-even in low half, per mma layout).
__device__ __forceinline__ void split2(float f0, float f1, uint32_t& hi, uint32_t& lo) {
    __nv_bfloat162 h2 = __float22bfloat162_rn(make_float2(f0, f1));
    float2 hf = __bfloat1622float2(h2);
    __nv_bfloat162 l2 = __float22bfloat162_rn(make_float2(f0 - hf.x, f1 - hf.y));
    hi = *reinterpret_cast<uint32_t*>(&h2);
    lo = *reinterpret_cast<uint32_t*>(&l2);
}

// ------------------------------ warp-MMA GEMM with in-register bf16 3-term split
// Out[bb][ot*128+m][jt*128+n] = (sum_c W[m][c] * F[bb][c][n] + bias[m]) * scale
// CTA 128x128, K-chunks of 32, 8 warps (4m x 2n), warp tile 32x64.
// SMEM per stage: A fp32 [128][32] rows padded to 40 words; B fp32 [32][128]
// rows padded to 132 words. All fragment loads + cp.async stores conflict-free.
#define AS_STRIDE 40
#define BS_STRIDE 132
#define ST_WORDS (128 * AS_STRIDE + 32 * BS_STRIDE)   // 9344
#define STG_BYTES (ST_WORDS * 4)                      // 37376
#define B_OFF_B  (128 * AS_STRIDE * 4)                // 20480 bytes

__global__ __launch_bounds__(256, 1)
void gemm_mma(const float* __restrict__ W, const float* __restrict__ F,
              const float* __restrict__ bias, float* __restrict__ Out,
              int J, float scale) {
    extern __shared__ float smf[];
    const int t = threadIdx.x, lane = t & 31;
    const int wid = t >> 5, wm = wid & 3, wn = wid >> 2;
    const int jt = blockIdx.x, ot = blockIdx.y, bb = blockIdx.z;
    const uint32_t sb = smem_u32(smf);

    const float* gW = W + (size_t)(ot * 128) * C_DIM;
    const float* gF = F + (size_t)bb * C_DIM * J + (size_t)jt * 128;

    float acc[2][8][4];
#pragma unroll
    for (int mt = 0; mt < 2; mt++)
#pragma unroll
        for (int nt = 0; nt < 8; nt++)
#pragma unroll
            for (int r = 0; r < 4; r++) acc[mt][nt][r] = 0.f;

#pragma unroll 1
    for (int i = 0; i < 9; i++) {
        // ---- issue async fp32 loads for k-chunk i (i = 0..7)
        if (i < 8) {
            const uint32_t a0 = sb + (uint32_t)(i & 1) * STG_BYTES;
            const uint32_t b0 = a0 + B_OFF_B;
#pragma unroll
            for (int j = 0; j < 4; j++) {
                int ch = t + 256 * j;
                // A: 1024 chunks of 16B: row m = ch>>3 (0..127), c = ch&7
                int am = ch >> 3, ac = ch & 7;
                cp16(a0 + (uint32_t)(am * (AS_STRIDE * 4) + ac * 16),
                     gW + (size_t)am * C_DIM + i * 32 + ac * 4);
                // B: 1024 chunks: row k = ch>>5 (0..31), c = ch&31
                int bk = ch >> 5, bc = ch & 31;
                cp16(b0 + (uint32_t)(bk * (BS_STRIDE * 4) + bc * 16),
                     gF + (size_t)(i * 32 + bk) * J + bc * 4);
            }
            CP_COMMIT();
        }
        if (i == 0) continue;
        if (i < 8) { CP_WAIT1(); } else { CP_WAIT0(); }
        __syncthreads();

        // ---- compute k-chunk i-1
        const float* As = smf + ((i - 1) & 1) * ST_WORDS;
        const float* Bs = As + 128 * AS_STRIDE;
#pragma unroll
        for (int ks = 0; ks < 2; ks++) {
            const int k0 = ks * 16 + (lane & 3) * 2;
            uint32_t ahi[2][4], alo[2][4];
#pragma unroll
            for (int mt = 0; mt < 2; mt++) {
                const int r0 = wm * 32 + mt * 16 + (lane >> 2);
                float2 f00 = *(const float2*)&As[r0 * AS_STRIDE + k0];
                float2 f10 = *(const float2*)&As[(r0 + 8) * AS_STRIDE + k0];
                float2 f01 = *(const float2*)&As[r0 * AS_STRIDE + k0 + 8];
                float2 f11 = *(const float2*)&As[(r0 + 8) * AS_STRIDE + k0 + 8];
                split2(f00.x, f00.y, ahi[mt][0], alo[mt][0]);
                split2(f10.x, f10.y, ahi[mt][1], alo[mt][1]);
                split2(f01.x, f01.y, ahi[mt][2], alo[mt][2]);
                split2(f11.x, f11.y, ahi[mt][3], alo[mt][3]);
            }
#pragma unroll
            for (int np = 0; np < 8; np++) {
                const int n = wn * 64 + np * 8 + (lane >> 2);
                float b00 = Bs[k0 * BS_STRIDE + n];
                float b01 = Bs[(k0 + 1) * BS_STRIDE + n];
                float b10 = Bs[(k0 + 8) * BS_STRIDE + n];
                float b11 = Bs[(k0 + 9) * BS_STRIDE + n];
                uint32_t bh[2], bl[2];
                split2(b00, b01, bh[0], bl[0]);
                split2(b10, b11, bh[1], bl[1]);
#pragma unroll
                for (int mt = 0; mt < 2; mt++) {
                    mma16816(acc[mt][np], ahi[mt], bh);   // Ahi * Bhi
                    mma16816(acc[mt][np], ahi[mt], bl);   // Ahi * Blo
                    mma16816(acc[mt][np], alo[mt], bh);   // Alo * Bhi
                }
            }
        }
        __syncthreads();
    }

    // ---- epilogue: (acc + bias) * scale
#pragma unroll
    for (int mt = 0; mt < 2; mt++)
#pragma unroll
        for (int half = 0; half < 2; half++) {
            int o = ot * 128 + wm * 32 + mt * 16 + half * 8 + (lane >> 2);
            float bi = bias[o];
            float* orow = Out + ((size_t)bb * C_DIM + o) * J
                        + (size_t)jt * 128 + wn * 64 + (lane & 3) * 2;
#pragma unroll
            for (int nt = 0; nt < 8; nt++) {
                float2 v;
                v.x = (acc[mt][nt][half * 2 + 0] + bi) * scale;
                v.y = (acc[mt][nt][half * 2 + 1] + bi) * scale;
                *(float2*)(orow + nt * 8) = v;
            }
        }
}

// ------------------------------ attention (unchanged; DRAM-bound)
__global__ __launch_bounds__(256)
void attn_kernel(const float* __restrict__ q, const float* __restrict__ k,
                 const float* __restrict__ v, float* __restrict__ out) {
    int t = blockIdx.x * blockDim.x + threadIdx.x;
    int x = t & 63;
    int y = (t >> 6) & 63;
    int head = (t >> 12) & 7;
    int b = t >> 15;

    const size_t chq = (size_t)(b * C_DIM + head * 32);
    const float* qb = q + chq * HW + y * 64 + x;
    const size_t fbase = chq * HWF + (size_t)(4 * y) * 256 + 4 * x;
    const float* kb = k + fbase;
    const float* vb = v + fbase;

    float logit[16];
#pragma unroll
    for (int p = 0; p < 16; p++) logit[p] = 0.f;

#pragma unroll 4
    for (int d = 0; d < 32; d++) {
        float qd = qb[(size_t)d * HW];
#pragma unroll
        for (int dy = 0; dy < 4; dy++) {
            float4 kv = *(const float4*)(kb + (size_t)d * HWF + dy * 256);
            logit[dy * 4 + 0] = fmaf(qd, kv.x, logit[dy * 4 + 0]);
            logit[dy * 4 + 1] = fmaf(qd, kv.y, logit[dy * 4 + 1]);
            logit[dy * 4 + 2] = fmaf(qd, kv.z, logit[dy * 4 + 2]);
            logit[dy * 4 + 3] = fmaf(qd, kv.w, logit[dy * 4 + 3]);
        }
    }

    float m = logit[0];
#pragma unroll
    for (int p = 1; p < 16; p++) m = fmaxf(m, logit[p]);
    float s = 0.f;
#pragma unroll
    for (int p = 0; p < 16; p++) { logit[p] = __expf(logit[p] - m); s += logit[p]; }
    float inv = 1.f / s;
#pragma unroll
    for (int p = 0; p < 16; p++) logit[p] *= inv;

    float* ob = out + chq * HW + y * 64 + x;
#pragma unroll 4
    for (int d = 0; d < 32; d++) {
        float sum = 0.f;
#pragma unroll
        for (int dy = 0; dy < 4; dy++) {
            float4 vv = *(const float4*)(vb + (size_t)d * HWF + dy * 256);
            sum = fmaf(logit[dy * 4 + 0], vv.x, sum);
            sum = fmaf(logit[dy * 4 + 1], vv.y, sum);
            sum = fmaf(logit[dy * 4 + 2], vv.z, sum);
            sum = fmaf(logit[dy * 4 + 3], vv.w, sum);
        }
        ob[(size_t)d * HW] = sum;
    }
}

// ------------------------------ launch
extern "C" void kernel_launch(void* const* d_in, const int* in_sizes, int n_in,
                              void* d_out, int out_size) {
    const float* x  = (const float*)d_in[0];
    const float* fm = (const float*)d_in[1];
    const float* Wq = (const float*)d_in[2];
    const float* bq = (const float*)d_in[3];
    const float* Wk = (const float*)d_in[4];
    const float* bk = (const float*)d_in[5];
    const float* Wv = (const float*)d_in[6];
    const float* bv = (const float*)d_in[7];
    float* out = (float*)d_out;

    float *q, *k, *v;
    cudaGetSymbolAddress((void**)&q, g_q);
    cudaGetSymbolAddress((void**)&k, g_k);
    cudaGetSymbolAddress((void**)&v, g_v);

    cudaFuncSetAttribute(gemm_mma, cudaFuncAttributeMaxDynamicSharedMemorySize,
                         2 * STG_BYTES);

    const float scaling = 0.17677669529663687f;  // 32^-0.5

    gemm_mma<<<dim3(HW / 128, 2, 2), 256, 2 * STG_BYTES>>>(Wq, x, bq, q, HW, scaling);
    gemm_mma<<<dim3(HWF / 128, 2, 2), 256, 2 * STG_BYTES>>>(Wk, fm, bk, k, HWF, 1.0f);
    gemm_mma<<<dim3(HWF / 128, 2, 2), 256, 2 * STG_BYTES>>>(Wv, fm, bv, v, HWF, 1.0f);

    attn_kernel<<<(2 * 8 * HW) / 256, 256>>>(q, k, v, out);
}